// round 1
// baseline (speedup 1.0000x reference)
#include <cuda_runtime.h>

// path_generator_GAD: N=131072 paths, T=251 (250 sequential steps).
// s_{t} = s + (b0 + b1*s)*dt + (a0 + a1*max(s,0))^g * Z*sqrt(dt)
// coefficients are affine maps of U(0,1) inputs.
//
// Strategy: warp-per-32-paths, 16-step tiles staged through padded shared
// memory so all global traffic is row-contiguous (coalesced). Z tile is
// reused as the output staging tile after consumption.

#define TSTEPS   251
#define DT_F     0.004f
#define SQRT_DT  0.063245553203367586f
#define S0_F     100.0f
#define TW       16          // timesteps per tile
#define TSTRIDE  17          // padded smem row stride (conflict-free)
#define WPB      8           // warps per block
#define NTILES   16          // ceil(250/16)

__global__ __launch_bounds__(WPB * 32, 2)
void gad_kernel(const float* __restrict__ Z,
                const float* __restrict__ Ua0,
                const float* __restrict__ Ua1,
                const float* __restrict__ Ub0,
                const float* __restrict__ Ub1,
                const float* __restrict__ Ug,
                float* __restrict__ out)
{
    extern __shared__ float smem[];
    const int warp = threadIdx.x >> 5;
    const int lane = threadIdx.x & 31;

    // 6 tiles of 32 x TSTRIDE floats per warp
    float* tZ  = smem + warp * (6 * 32 * TSTRIDE);
    float* tA0 = tZ  + 32 * TSTRIDE;
    float* tA1 = tA0 + 32 * TSTRIDE;
    float* tB0 = tA1 + 32 * TSTRIDE;
    float* tB1 = tB0 + 32 * TSTRIDE;
    float* tG  = tB1 + 32 * TSTRIDE;

    const int pBase = (blockIdx.x * WPB + warp) << 5;   // first path of this warp

    // column 0 of the output is S0 (scattered 4B writes, negligible volume)
    out[(pBase + lane) * TSTEPS] = S0_F;

    const int tcol = lane & 15;   // timestep within tile handled by this lane (load/store phase)
    const int prow = lane >> 4;   // 0/1: which of two rows this half-warp loads

    float s = S0_F;

    for (int k = 0; k < NTILES; ++k) {
        const int t0 = 1 + k * TW;
        const int w  = min(TW, TSTEPS - t0);   // 16 except last tile (10)
        const bool act = (tcol < w);

        __syncwarp();
        // ---- load phase: row-contiguous (coalesced) global -> smem transpose ----
        #pragma unroll
        for (int r = 0; r < 32; r += 2) {
            const int row = r + prow;
            const int gi  = (pBase + row) * TSTEPS + t0 + tcol;
            const int si  = row * TSTRIDE + tcol;
            if (act) {
                tZ [si] = Z  [gi];
                tA0[si] = Ua0[gi];
                tA1[si] = Ua1[gi];
                tB0[si] = Ub0[gi];
                tB1[si] = Ub1[gi];
                tG [si] = Ug [gi];
            }
        }
        __syncwarp();

        // ---- compute phase: each lane advances its own path from smem ----
        const int sb = lane * TSTRIDE;

        #define GAD_STEP(J)                                              \
        {                                                                 \
            const int si = sb + (J);                                      \
            float a0 = fmaf(tA0[si], 0.10f, 0.05f);                       \
            float a1 = fmaf(tA1[si], 0.20f, 0.10f);                       \
            float b0 = tB0[si] * 0.05f;                                   \
            float b1 = tB1[si] * 0.10f;                                   \
            float g  = fmaf(tG[si], 0.20f, 0.80f);                        \
            float zt = tZ[si] * SQRT_DT;                                  \
            float base = fmaf(a1, fmaxf(s, 0.0f), a0);                    \
            s = fmaf(fmaf(b1, s, b0), DT_F, s) + powf(base, g) * zt;      \
            tZ[si] = s;  /* stage output into consumed Z slot */          \
        }

        if (w == TW) {
            #pragma unroll
            for (int j = 0; j < TW; ++j) GAD_STEP(j)
        } else {
            for (int j = 0; j < w; ++j) GAD_STEP(j)
        }
        #undef GAD_STEP

        __syncwarp();
        // ---- store phase: smem -> coalesced global writes ----
        #pragma unroll
        for (int r = 0; r < 32; r += 2) {
            const int row = r + prow;
            if (act)
                out[(pBase + row) * TSTEPS + t0 + tcol] = tZ[row * TSTRIDE + tcol];
        }
    }
}

extern "C" void kernel_launch(void* const* d_in, const int* in_sizes, int n_in,
                              void* d_out, int out_size)
{
    const float* Z   = (const float*)d_in[0];
    const float* Ua0 = (const float*)d_in[1];
    const float* Ua1 = (const float*)d_in[2];
    const float* Ub0 = (const float*)d_in[3];
    const float* Ub1 = (const float*)d_in[4];
    const float* Ug  = (const float*)d_in[5];
    float* out = (float*)d_out;

    const int N = in_sizes[0] / TSTEPS;          // 131072
    const int pathsPerBlock = WPB * 32;          // 256
    const int blocks = (N + pathsPerBlock - 1) / pathsPerBlock;

    const size_t smem = (size_t)WPB * 6 * 32 * TSTRIDE * sizeof(float); // 104448 B
    cudaFuncSetAttribute(gad_kernel, cudaFuncAttributeMaxDynamicSharedMemorySize, (int)smem);

    gad_kernel<<<blocks, pathsPerBlock, smem>>>(Z, Ua0, Ua1, Ub0, Ub1, Ug, out);
}

// round 3
// speedup vs baseline: 1.1037x; 1.1037x over previous
#include <cuda_runtime.h>
#include <cstdint>

// path_generator_GAD: N=131072 paths, T=251 (250 sequential steps).
// s_{t+1} = s + (b0 + b1*s)*dt + (a0 + a1*max(s,0))^g * Z*sqrt(dt)
//
// R3: cp.async (LDGSTS) double-buffered tile pipeline (R2 + compile fix).
//  - warp owns 32 paths; 16-step tiles of all 6 inputs staged to smem via
//    4-byte cp.async (rows are only 4B-aligned: T=251 -> 1004B stride)
//  - 2-tile-deep async pipeline: compute tile k while tile k+1 streams in
//  - transpose in smem (stride 17 -> conflict-free)
//  - __powf intrinsic (base >= 0.05 always, err ~1e-5 << 1e-3 tol)

#define TSTEPS   251
#define DT_F     0.004f
#define SQRT_DT  0.063245553203367586f
#define S0_F     100.0f
#define TW       16                       // timesteps per tile
#define TSTRIDE  17                       // padded smem row stride
#define WPB      8                        // warps per block
#define NTILES   16                       // ceil(250/16)
#define ARRF     (32 * TSTRIDE)           // floats per array tile
#define WARPF    (6 * ARRF)               // floats per warp per buffer
#define BUFF     (WPB * WARPF)            // floats per buffer (all warps)

__device__ __forceinline__ void cp4(unsigned int saddr, const float* g) {
    asm volatile("cp.async.ca.shared.global [%0], [%1], 4;" :: "r"(saddr), "l"(g));
}
__device__ __forceinline__ void cp_commit() {
    asm volatile("cp.async.commit_group;");
}
__device__ __forceinline__ void cp_wait1() {
    asm volatile("cp.async.wait_group 1;");
}

__global__ __launch_bounds__(WPB * 32, 1)
void gad_kernel(const float* __restrict__ Z,
                const float* __restrict__ Ua0,
                const float* __restrict__ Ua1,
                const float* __restrict__ Ub0,
                const float* __restrict__ Ub1,
                const float* __restrict__ Ug,
                float* __restrict__ out)
{
    extern __shared__ float smem[];
    const int warp = threadIdx.x >> 5;
    const int lane = threadIdx.x & 31;
    const int tcol = lane & 15;          // timestep within tile (load/store role)
    const int prow = lane >> 4;          // 0/1: row parity for this half-warp
    const int pBase = (blockIdx.x * WPB + warp) << 5;

    const unsigned int smem_u32 = (unsigned int)__cvta_generic_to_shared(smem);

    out[(pBase + lane) * TSTEPS] = S0_F;  // column 0 = S0

    // issue all 6 arrays' tile k into buffer b (async), then commit a group
#define ISSUE_TILE(k, b)                                                     \
    {                                                                        \
        const int t0_ = 1 + (k) * TW;                                        \
        if (t0_ + tcol < TSTEPS) {                                           \
            const unsigned int sw =                                          \
                smem_u32 + (unsigned int)(((b) * BUFF + warp * WARPF) * 4);  \
            _Pragma("unroll")                                                \
            for (int r = 0; r < 32; r += 2) {                                \
                const int row_ = r + prow;                                   \
                const int gi_  = (pBase + row_) * TSTEPS + t0_ + tcol;       \
                const unsigned int so =                                      \
                    sw + (unsigned int)((row_ * TSTRIDE + tcol) * 4);        \
                cp4(so + 0u * (ARRF * 4), Z   + gi_);                        \
                cp4(so + 1u * (ARRF * 4), Ua0 + gi_);                        \
                cp4(so + 2u * (ARRF * 4), Ua1 + gi_);                        \
                cp4(so + 3u * (ARRF * 4), Ub0 + gi_);                        \
                cp4(so + 4u * (ARRF * 4), Ub1 + gi_);                        \
                cp4(so + 5u * (ARRF * 4), Ug  + gi_);                        \
            }                                                                \
        }                                                                    \
        cp_commit();                                                         \
    }

    // prime the 2-deep pipeline
    ISSUE_TILE(0, 0)
    ISSUE_TILE(1, 1)

    float s = S0_F;

    for (int k = 0; k < NTILES; ++k) {
        const int buf = k & 1;
        const int t0  = 1 + k * TW;
        const int w   = min(TW, TSTEPS - t0);   // 16 except last tile (10)

        cp_wait1();          // tile k complete (<=1 group pending)
        __syncwarp();        // make peers' cp.async data visible

        float* B   = smem + buf * BUFF + warp * WARPF;
        float* tZ  = B;
        float* tA0 = B + 1 * ARRF;
        float* tA1 = B + 2 * ARRF;
        float* tB0 = B + 3 * ARRF;
        float* tB1 = B + 4 * ARRF;
        float* tG  = B + 5 * ARRF;

        const int sb = lane * TSTRIDE;

#define GAD_STEP(J)                                                   \
        {                                                             \
            const int si = sb + (J);                                  \
            float a0 = fmaf(tA0[si], 0.10f, 0.05f);                   \
            float a1 = fmaf(tA1[si], 0.20f, 0.10f);                   \
            float b0 = tB0[si] * 0.05f;                               \
            float b1 = tB1[si] * 0.10f;                               \
            float g  = fmaf(tG[si], 0.20f, 0.80f);                    \
            float zt = tZ[si] * SQRT_DT;                              \
            float base = fmaf(a1, fmaxf(s, 0.0f), a0);                \
            s = fmaf(fmaf(b1, s, b0), DT_F, s) + __powf(base, g) * zt;\
            tZ[si] = s;  /* stage output into consumed Z slot */      \
        }

        if (w == TW) {
            #pragma unroll
            for (int j = 0; j < TW; ++j) GAD_STEP(j)
        } else {
            for (int j = 0; j < w; ++j) GAD_STEP(j)
        }
#undef GAD_STEP

        __syncwarp();
        // coalesced write-back from the staged tZ tile
        if (tcol < w) {
            #pragma unroll
            for (int r = 0; r < 32; r += 2) {
                const int row = r + prow;
                out[(pBase + row) * TSTEPS + t0 + tcol] =
                    tZ[row * TSTRIDE + tcol];
            }
        }
        __syncwarp();        // all lanes done reading buf before refill

        if (k + 2 < NTILES) {
            ISSUE_TILE(k + 2, buf)
        } else {
            cp_commit();     // keep group accounting aligned for cp_wait1
        }
    }
#undef ISSUE_TILE
}

extern "C" void kernel_launch(void* const* d_in, const int* in_sizes, int n_in,
                              void* d_out, int out_size)
{
    const float* Z   = (const float*)d_in[0];
    const float* Ua0 = (const float*)d_in[1];
    const float* Ua1 = (const float*)d_in[2];
    const float* Ub0 = (const float*)d_in[3];
    const float* Ub1 = (const float*)d_in[4];
    const float* Ug  = (const float*)d_in[5];
    float* out = (float*)d_out;

    const int N = in_sizes[0] / TSTEPS;          // 131072
    const int pathsPerBlock = WPB * 32;          // 256
    const int blocks = (N + pathsPerBlock - 1) / pathsPerBlock;

    const size_t smem = (size_t)2 * BUFF * sizeof(float);   // 208896 B
    cudaFuncSetAttribute(gad_kernel, cudaFuncAttributeMaxDynamicSharedMemorySize, (int)smem);

    gad_kernel<<<blocks, pathsPerBlock, smem>>>(Z, Ua0, Ua1, Ub0, Ub1, Ug, out);
}